// round 1
// baseline (speedup 1.0000x reference)
#include <cuda_runtime.h>
#include <math_constants.h>

#define N_NODES 100000
#define N_EDGES 3200000
#define E_TOT   (N_EDGES + N_NODES)   // edges + self loops
#define F_IN    128
#define HID     32
#define NCLS    40
#define NEG_SLOPE 0.2f

// ---------------- scratch (device globals; no allocs allowed) ----------------
__device__ float g_h1[N_NODES * HID];     // x @ W1
__device__ float g_s1[N_NODES];           // h1 . a_src1
__device__ float g_d1[N_NODES];           // h1 . a_dst1
__device__ float g_x2[N_NODES * HID];     // relu(agg1 + b1)
__device__ float g_h2[N_NODES * NCLS];    // x2 @ W2
__device__ float g_s2[N_NODES];
__device__ float g_d2[N_NODES];
__device__ int   g_deg[N_NODES];
__device__ int   g_rowptr[N_NODES + 1];
__device__ int   g_cursor[N_NODES];
__device__ int   g_csr_src[E_TOT];

// ---------------- CSR build ----------------
__global__ void k_init_deg() {
    int i = blockIdx.x * blockDim.x + threadIdx.x;
    if (i < N_NODES) g_deg[i] = 1;  // self loop
}

__global__ void k_hist(const int* __restrict__ dst) {
    int i = blockIdx.x * blockDim.x + threadIdx.x;
    if (i < N_EDGES) atomicAdd(&g_deg[dst[i]], 1);
}

// single block, 1024 threads: exclusive scan of g_deg -> g_rowptr, g_cursor
__global__ void k_scan() {
    __shared__ int parts[1024];
    int t = threadIdx.x;
    const int chunk = (N_NODES + 1023) / 1024;
    int beg = t * chunk;
    int end = min(beg + chunk, N_NODES);
    int s = 0;
    for (int i = beg; i < end; i++) s += g_deg[i];
    parts[t] = s;
    __syncthreads();
    // Hillis-Steele inclusive scan
    for (int off = 1; off < 1024; off <<= 1) {
        int v = (t >= off) ? parts[t - off] : 0;
        __syncthreads();
        parts[t] += v;
        __syncthreads();
    }
    int run = parts[t] - s;  // exclusive prefix
    for (int i = beg; i < end; i++) {
        g_rowptr[i] = run;
        g_cursor[i] = run;
        run += g_deg[i];
    }
    if (t == 1023) g_rowptr[N_NODES] = run;
}

__global__ void k_scatter(const int* __restrict__ src, const int* __restrict__ dst) {
    int i = blockIdx.x * blockDim.x + threadIdx.x;
    if (i >= E_TOT) return;
    int s, d;
    if (i < N_EDGES) { s = src[i]; d = dst[i]; }
    else             { s = d = i - N_EDGES; }
    int p = atomicAdd(&g_cursor[d], 1);
    g_csr_src[p] = s;
}

// ---------------- GEMM1: h1 = x @ W1, s1/d1 attention projections ----------------
__global__ __launch_bounds__(256) void k_gemm1(const float* __restrict__ x,
                                               const float* __restrict__ W1,
                                               const float* __restrict__ a_src,
                                               const float* __restrict__ a_dst) {
    __shared__ float Ws[F_IN * HID];
    __shared__ float asv[HID], adv[HID];
    for (int i = threadIdx.x; i < F_IN * HID; i += blockDim.x) Ws[i] = W1[i];
    if (threadIdx.x < HID) { asv[threadIdx.x] = a_src[threadIdx.x]; adv[threadIdx.x] = a_dst[threadIdx.x]; }
    __syncthreads();

    int n = blockIdx.x * blockDim.x + threadIdx.x;
    if (n >= N_NODES) return;

    float acc[HID];
#pragma unroll
    for (int c = 0; c < HID; c++) acc[c] = 0.f;

    const float4* xr = reinterpret_cast<const float4*>(x + (size_t)n * F_IN);
#pragma unroll 4
    for (int k4 = 0; k4 < F_IN / 4; k4++) {
        float4 xv = xr[k4];
        const float* w = &Ws[(k4 * 4) * HID];
#pragma unroll
        for (int c = 0; c < HID; c++) {
            acc[c] = fmaf(xv.x, w[c], acc[c]);
            acc[c] = fmaf(xv.y, w[HID + c], acc[c]);
            acc[c] = fmaf(xv.z, w[2 * HID + c], acc[c]);
            acc[c] = fmaf(xv.w, w[3 * HID + c], acc[c]);
        }
    }
    float sv = 0.f, dv = 0.f;
#pragma unroll
    for (int c = 0; c < HID; c++) {
        g_h1[(size_t)n * HID + c] = acc[c];
        sv = fmaf(acc[c], asv[c], sv);
        dv = fmaf(acc[c], adv[c], dv);
    }
    g_s1[n] = sv;
    g_d1[n] = dv;
}

// ---------------- layer-1 aggregate: warp per dst node, online softmax ----------------
__global__ __launch_bounds__(256) void k_agg1(const float* __restrict__ b1) {
    int warp = (blockIdx.x * blockDim.x + threadIdx.x) >> 5;
    int lane = threadIdx.x & 31;
    if (warp >= N_NODES) return;
    int n = warp;
    int beg = g_rowptr[n], end = g_rowptr[n + 1];
    float dn = g_d1[n];

    float mx = -CUDART_INF_F, den = 0.f, acc = 0.f;

    int   s_nx  = g_csr_src[beg];
    float ss_nx = g_s1[s_nx];
    float h_nx  = g_h1[(size_t)s_nx * HID + lane];

    for (int e = beg; e < end; e++) {
        float ss = ss_nx, h = h_nx;
        if (e + 1 < end) {
            int s2 = g_csr_src[e + 1];
            ss_nx = g_s1[s2];
            h_nx  = g_h1[(size_t)s2 * HID + lane];
        }
        float ev = ss + dn;
        ev = ev > 0.f ? ev : NEG_SLOPE * ev;
        float nm = fmaxf(mx, ev);
        float sc = __expf(mx - nm);   // 0 when mx = -inf
        float p  = __expf(ev - nm);
        den = den * sc + p;
        acc = fmaf(acc, sc, p * h);
        mx = nm;
    }
    float v = acc / den + b1[lane];
    g_x2[(size_t)n * HID + lane] = fmaxf(v, 0.f);
}

// ---------------- GEMM2: h2 = x2 @ W2, s2/d2 ----------------
__global__ __launch_bounds__(256) void k_gemm2(const float* __restrict__ W2,
                                               const float* __restrict__ a_src,
                                               const float* __restrict__ a_dst) {
    __shared__ float Ws[HID * NCLS];
    __shared__ float asv[NCLS], adv[NCLS];
    for (int i = threadIdx.x; i < HID * NCLS; i += blockDim.x) Ws[i] = W2[i];
    if (threadIdx.x < NCLS) { asv[threadIdx.x] = a_src[threadIdx.x]; adv[threadIdx.x] = a_dst[threadIdx.x]; }
    __syncthreads();

    int n = blockIdx.x * blockDim.x + threadIdx.x;
    if (n >= N_NODES) return;

    float acc[NCLS];
#pragma unroll
    for (int c = 0; c < NCLS; c++) acc[c] = 0.f;

    const float4* xr = reinterpret_cast<const float4*>(&g_x2[(size_t)n * HID]);
#pragma unroll
    for (int k4 = 0; k4 < HID / 4; k4++) {
        float4 xv = xr[k4];
        const float* w = &Ws[(k4 * 4) * NCLS];
#pragma unroll
        for (int c = 0; c < NCLS; c++) {
            acc[c] = fmaf(xv.x, w[c], acc[c]);
            acc[c] = fmaf(xv.y, w[NCLS + c], acc[c]);
            acc[c] = fmaf(xv.z, w[2 * NCLS + c], acc[c]);
            acc[c] = fmaf(xv.w, w[3 * NCLS + c], acc[c]);
        }
    }
    float sv = 0.f, dv = 0.f;
#pragma unroll
    for (int c = 0; c < NCLS; c++) {
        g_h2[(size_t)n * NCLS + c] = acc[c];
        sv = fmaf(acc[c], asv[c], sv);
        dv = fmaf(acc[c], adv[c], dv);
    }
    g_s2[n] = sv;
    g_d2[n] = dv;
}

// ---------------- layer-2 aggregate + bias + relu + log_softmax ----------------
__global__ __launch_bounds__(256) void k_agg2(const float* __restrict__ b2,
                                              float* __restrict__ out) {
    int warp = (blockIdx.x * blockDim.x + threadIdx.x) >> 5;
    int lane = threadIdx.x & 31;
    if (warp >= N_NODES) return;
    int n = warp;
    bool has2 = lane < (NCLS - 32);   // lanes 0..7 also own channel lane+32
    int beg = g_rowptr[n], end = g_rowptr[n + 1];
    float dn = g_d2[n];

    float mx = -CUDART_INF_F, den = 0.f, acc0 = 0.f, acc1 = 0.f;

    int   s_nx  = g_csr_src[beg];
    float ss_nx = g_s2[s_nx];
    float h0_nx = g_h2[(size_t)s_nx * NCLS + lane];
    float h1_nx = has2 ? g_h2[(size_t)s_nx * NCLS + lane + 32] : 0.f;

    for (int e = beg; e < end; e++) {
        float ss = ss_nx, h0 = h0_nx, h1v = h1_nx;
        if (e + 1 < end) {
            int s2 = g_csr_src[e + 1];
            ss_nx = g_s2[s2];
            h0_nx = g_h2[(size_t)s2 * NCLS + lane];
            h1_nx = has2 ? g_h2[(size_t)s2 * NCLS + lane + 32] : 0.f;
        }
        float ev = ss + dn;
        ev = ev > 0.f ? ev : NEG_SLOPE * ev;
        float nm = fmaxf(mx, ev);
        float sc = __expf(mx - nm);
        float p  = __expf(ev - nm);
        den  = den * sc + p;
        acc0 = fmaf(acc0, sc, p * h0);
        acc1 = fmaf(acc1, sc, p * h1v);
        mx = nm;
    }
    float inv = 1.f / den;
    float v0 = fmaxf(acc0 * inv + b2[lane], 0.f);
    float v1 = has2 ? fmaxf(acc1 * inv + b2[lane + 32], 0.f) : -CUDART_INF_F;

    // log_softmax over 40 values spread across the warp
    float m = fmaxf(v0, v1);
#pragma unroll
    for (int o = 16; o > 0; o >>= 1) m = fmaxf(m, __shfl_xor_sync(0xffffffffu, m, o));
    float se = __expf(v0 - m) + (has2 ? __expf(v1 - m) : 0.f);
#pragma unroll
    for (int o = 16; o > 0; o >>= 1) se += __shfl_xor_sync(0xffffffffu, se, o);
    float lse = m + logf(se);

    out[(size_t)n * NCLS + lane] = v0 - lse;
    if (has2) out[(size_t)n * NCLS + lane + 32] = v1 - lse;
}

// ---------------- launch ----------------
extern "C" void kernel_launch(void* const* d_in, const int* in_sizes, int n_in,
                              void* d_out, int out_size) {
    const float* x        = (const float*)d_in[0];
    const int*   edge     = (const int*)  d_in[1];
    const float* W1       = (const float*)d_in[2];
    const float* att_src1 = (const float*)d_in[3];
    const float* att_dst1 = (const float*)d_in[4];
    const float* b1       = (const float*)d_in[5];
    const float* W2       = (const float*)d_in[6];
    const float* att_src2 = (const float*)d_in[7];
    const float* att_dst2 = (const float*)d_in[8];
    const float* b2       = (const float*)d_in[9];
    float* out = (float*)d_out;

    const int* src = edge;
    const int* dst = edge + N_EDGES;

    k_init_deg<<<(N_NODES + 255) / 256, 256>>>();
    k_hist<<<(N_EDGES + 255) / 256, 256>>>(dst);
    k_scan<<<1, 1024>>>();
    k_scatter<<<(E_TOT + 255) / 256, 256>>>(src, dst);

    k_gemm1<<<(N_NODES + 255) / 256, 256>>>(x, W1, att_src1, att_dst1);
    k_agg1<<<(N_NODES * 32 + 255) / 256, 256>>>(b1);
    k_gemm2<<<(N_NODES + 255) / 256, 256>>>(W2, att_src2, att_dst2);
    k_agg2<<<(N_NODES * 32 + 255) / 256, 256>>>(b2, out);
}

// round 2
// speedup vs baseline: 1.3626x; 1.3626x over previous
#include <cuda_runtime.h>
#include <math_constants.h>

#define N_NODES 100000
#define N_EDGES 3200000
#define E_TOT   (N_EDGES + N_NODES)   // edges + self loops
#define F_IN    128
#define HID     32
#define NCLS    40
#define NEG_SLOPE 0.2f
#define NBLK_SCAN 98                  // ceil(100000/1024)

// ---------------- scratch (device globals; no allocs allowed) ----------------
__device__ float g_h1[N_NODES * HID];     // x @ W1
__device__ float g_s1[N_NODES];           // h1 . a_src1
__device__ float g_d1[N_NODES];           // h1 . a_dst1
__device__ float g_x2[N_NODES * HID];     // relu(agg1 + b1)
__device__ float g_h2[N_NODES * NCLS];    // x2 @ W2
__device__ float g_s2[N_NODES];
__device__ float g_d2[N_NODES];
__device__ int   g_deg[N_NODES];
__device__ int   g_rowptr[N_NODES + 1];
__device__ int   g_cursor[N_NODES];
__device__ int   g_csr_src[E_TOT];
__device__ int   g_bsum[NBLK_SCAN];
__device__ int   g_boff[NBLK_SCAN];

// ---------------- CSR build ----------------
__global__ void k_init_deg() {
    int i = blockIdx.x * blockDim.x + threadIdx.x;
    if (i < N_NODES) g_deg[i] = 1;  // self loop
}

// 4 edges per thread
__global__ void k_hist(const int* __restrict__ dst) {
    int i = blockIdx.x * blockDim.x + threadIdx.x;   // i in [0, N_EDGES/4)
    if (i * 4 >= N_EDGES) return;
    int4 d = reinterpret_cast<const int4*>(dst)[i];
    atomicAdd(&g_deg[d.x], 1);
    atomicAdd(&g_deg[d.y], 1);
    atomicAdd(&g_deg[d.z], 1);
    atomicAdd(&g_deg[d.w], 1);
}

// block sums: NBLK_SCAN blocks x 256 threads, each block covers 1024 degs
__global__ void k_bsum() {
    __shared__ int sh[256];
    int t = threadIdx.x;
    int base = blockIdx.x * 1024 + t * 4;
    int s = 0;
#pragma unroll
    for (int k = 0; k < 4; k++) {
        int i = base + k;
        if (i < N_NODES) s += g_deg[i];
    }
    sh[t] = s;
    __syncthreads();
    for (int off = 128; off > 0; off >>= 1) {
        if (t < off) sh[t] += sh[t + off];
        __syncthreads();
    }
    if (t == 0) g_bsum[blockIdx.x] = sh[0];
}

// scan the NBLK_SCAN block sums (1 block)
__global__ void k_bscan() {
    __shared__ int sh[128];
    int t = threadIdx.x;
    int v = (t < NBLK_SCAN) ? g_bsum[t] : 0;
    sh[t] = v;
    __syncthreads();
    for (int off = 1; off < 128; off <<= 1) {
        int u = (t >= off) ? sh[t - off] : 0;
        __syncthreads();
        sh[t] += u;
        __syncthreads();
    }
    if (t < NBLK_SCAN) g_boff[t] = sh[t] - v;  // exclusive
    if (t == 0) g_rowptr[N_NODES] = E_TOT;
}

// per-block exclusive scan -> rowptr, cursor
__global__ void k_rowptr() {
    __shared__ int sh[256];
    int t = threadIdx.x;
    int base = blockIdx.x * 1024 + t * 4;
    int v[4];
    int s = 0;
#pragma unroll
    for (int k = 0; k < 4; k++) {
        int i = base + k;
        v[k] = (i < N_NODES) ? g_deg[i] : 0;
        s += v[k];
    }
    sh[t] = s;
    __syncthreads();
    for (int off = 1; off < 256; off <<= 1) {
        int u = (t >= off) ? sh[t - off] : 0;
        __syncthreads();
        sh[t] += u;
        __syncthreads();
    }
    int run = sh[t] - s + g_boff[blockIdx.x];
#pragma unroll
    for (int k = 0; k < 4; k++) {
        int i = base + k;
        if (i < N_NODES) { g_rowptr[i] = run; g_cursor[i] = run; }
        run += v[k];
    }
}

// 4 edges per thread
__global__ void k_scatter(const int* __restrict__ src, const int* __restrict__ dst) {
    int i = blockIdx.x * blockDim.x + threadIdx.x;
    if (i * 4 >= N_EDGES) return;
    int4 s4 = reinterpret_cast<const int4*>(src)[i];
    int4 d4 = reinterpret_cast<const int4*>(dst)[i];
    int p0 = atomicAdd(&g_cursor[d4.x], 1);
    int p1 = atomicAdd(&g_cursor[d4.y], 1);
    int p2 = atomicAdd(&g_cursor[d4.z], 1);
    int p3 = atomicAdd(&g_cursor[d4.w], 1);
    g_csr_src[p0] = s4.x;
    g_csr_src[p1] = s4.y;
    g_csr_src[p2] = s4.z;
    g_csr_src[p3] = s4.w;
}

__global__ void k_scatter_loops() {
    int i = blockIdx.x * blockDim.x + threadIdx.x;
    if (i >= N_NODES) return;
    int p = atomicAdd(&g_cursor[i], 1);
    g_csr_src[p] = i;
}

// ---------------- GEMM1: h1 = x @ W1, s1/d1 attention projections ----------------
__global__ __launch_bounds__(256) void k_gemm1(const float* __restrict__ x,
                                               const float* __restrict__ W1,
                                               const float* __restrict__ a_src,
                                               const float* __restrict__ a_dst) {
    __shared__ float Ws[F_IN * HID];
    __shared__ float asv[HID], adv[HID];
    for (int i = threadIdx.x; i < F_IN * HID; i += blockDim.x) Ws[i] = W1[i];
    if (threadIdx.x < HID) { asv[threadIdx.x] = a_src[threadIdx.x]; adv[threadIdx.x] = a_dst[threadIdx.x]; }
    __syncthreads();

    int n = blockIdx.x * blockDim.x + threadIdx.x;
    if (n >= N_NODES) return;

    float acc[HID];
#pragma unroll
    for (int c = 0; c < HID; c++) acc[c] = 0.f;

    const float4* xr = reinterpret_cast<const float4*>(x + (size_t)n * F_IN);
#pragma unroll 4
    for (int k4 = 0; k4 < F_IN / 4; k4++) {
        float4 xv = xr[k4];
        const float* w = &Ws[(k4 * 4) * HID];
#pragma unroll
        for (int c = 0; c < HID; c++) {
            acc[c] = fmaf(xv.x, w[c], acc[c]);
            acc[c] = fmaf(xv.y, w[HID + c], acc[c]);
            acc[c] = fmaf(xv.z, w[2 * HID + c], acc[c]);
            acc[c] = fmaf(xv.w, w[3 * HID + c], acc[c]);
        }
    }
    float sv = 0.f, dv = 0.f;
#pragma unroll
    for (int c = 0; c < HID; c++) {
        g_h1[(size_t)n * HID + c] = acc[c];
        sv = fmaf(acc[c], asv[c], sv);
        dv = fmaf(acc[c], adv[c], dv);
    }
    g_s1[n] = sv;
    g_d1[n] = dv;
}

// ---------------- online softmax update (branchless, -inf safe) ----------------
__device__ __forceinline__ void upd1(float& mx, float& den, float& acc,
                                     float sv, float dn, float h, bool valid) {
    float ev = sv + dn;
    ev = ev > 0.f ? ev : NEG_SLOPE * ev;
    if (!valid) ev = -CUDART_INF_F;
    float nm = fmaxf(mx, ev);
    float sc = __expf(mx - nm);
    float p  = __expf(ev - nm);
    den = den * sc + p;
    acc = fmaf(acc, sc, p * h);
    mx = nm;
}

__device__ __forceinline__ void upd2(float& mx, float& den, float& a0, float& a1,
                                     float sv, float dn, float h0, float h1, bool valid) {
    float ev = sv + dn;
    ev = ev > 0.f ? ev : NEG_SLOPE * ev;
    if (!valid) ev = -CUDART_INF_F;
    float nm = fmaxf(mx, ev);
    float sc = __expf(mx - nm);
    float p  = __expf(ev - nm);
    den = den * sc + p;
    a0 = fmaf(a0, sc, p * h0);
    a1 = fmaf(a1, sc, p * h1);
    mx = nm;
}

__device__ __forceinline__ void load_chunk1(int jj, int idxreg, int cntv, int lane,
                                            float s[4], float h[4]) {
    int i0 = __shfl_sync(0xffffffffu, idxreg, jj);
    int i1 = __shfl_sync(0xffffffffu, idxreg, min(jj + 1, cntv - 1));
    int i2 = __shfl_sync(0xffffffffu, idxreg, min(jj + 2, cntv - 1));
    int i3 = __shfl_sync(0xffffffffu, idxreg, min(jj + 3, cntv - 1));
    s[0] = g_s1[i0]; s[1] = g_s1[i1]; s[2] = g_s1[i2]; s[3] = g_s1[i3];
    h[0] = g_h1[i0 * HID + lane];
    h[1] = g_h1[i1 * HID + lane];
    h[2] = g_h1[i2 * HID + lane];
    h[3] = g_h1[i3 * HID + lane];
}

__device__ __forceinline__ void load_chunk2(int jj, int idxreg, int cntv, int lane, bool has2,
                                            float s[4], float h0[4], float h1[4]) {
    int i0 = __shfl_sync(0xffffffffu, idxreg, jj);
    int i1 = __shfl_sync(0xffffffffu, idxreg, min(jj + 1, cntv - 1));
    int i2 = __shfl_sync(0xffffffffu, idxreg, min(jj + 2, cntv - 1));
    int i3 = __shfl_sync(0xffffffffu, idxreg, min(jj + 3, cntv - 1));
    s[0] = g_s2[i0]; s[1] = g_s2[i1]; s[2] = g_s2[i2]; s[3] = g_s2[i3];
    h0[0] = g_h2[i0 * NCLS + lane];
    h0[1] = g_h2[i1 * NCLS + lane];
    h0[2] = g_h2[i2 * NCLS + lane];
    h0[3] = g_h2[i3 * NCLS + lane];
    int l2 = lane + 32;
    h1[0] = has2 ? g_h2[i0 * NCLS + l2] : 0.f;
    h1[1] = has2 ? g_h2[i1 * NCLS + l2] : 0.f;
    h1[2] = has2 ? g_h2[i2 * NCLS + l2] : 0.f;
    h1[3] = has2 ? g_h2[i3 * NCLS + l2] : 0.f;
}

// ---------------- layer-1 aggregate: warp per dst, batched idx + pipelined gathers ----
__global__ __launch_bounds__(256) void k_agg1(const float* __restrict__ b1) {
    int warp = (blockIdx.x * blockDim.x + threadIdx.x) >> 5;
    int lane = threadIdx.x & 31;
    if (warp >= N_NODES) return;
    int n = warp;
    int beg = g_rowptr[n], end = g_rowptr[n + 1];
    float dn = g_d1[n];

    float mx = -CUDART_INF_F, den = 0.f, acc = 0.f;

    int base = beg;
    int rem  = end - base;                 // >= 1 (self loop)
    int idx  = g_csr_src[base + min(lane, rem - 1)];
    int cnt  = min(rem, 32);
    int j = 0;

    float cs[4], ch[4];
    load_chunk1(j, idx, cnt, lane, cs, ch);
    int cval = cnt - j;

    while (true) {
        // prefetch next chunk
        int jn = j + 4;
        int idx2 = idx, cnt2 = cnt, base2 = base;
        bool have_next;
        if (jn < cnt) {
            have_next = true;
        } else {
            base2 = base + 32;
            int rem2 = end - base2;
            if (rem2 > 0) {
                idx2 = g_csr_src[base2 + min(lane, rem2 - 1)];
                cnt2 = min(rem2, 32);
                jn = 0;
                have_next = true;
            } else {
                have_next = false;
            }
        }
        float ns[4], nh[4];
        if (have_next) load_chunk1(jn, idx2, cnt2, lane, ns, nh);

        // math on current chunk
        upd1(mx, den, acc, cs[0], dn, ch[0], true);
        upd1(mx, den, acc, cs[1], dn, ch[1], cval > 1);
        upd1(mx, den, acc, cs[2], dn, ch[2], cval > 2);
        upd1(mx, den, acc, cs[3], dn, ch[3], cval > 3);

        if (!have_next) break;
        j = jn; idx = idx2; cnt = cnt2; base = base2;
#pragma unroll
        for (int k = 0; k < 4; k++) { cs[k] = ns[k]; ch[k] = nh[k]; }
        cval = cnt - j;
    }

    float v = acc / den + b1[lane];
    g_x2[(size_t)n * HID + lane] = fmaxf(v, 0.f);
}

// ---------------- GEMM2: h2 = x2 @ W2, s2/d2 ----------------
__global__ __launch_bounds__(256) void k_gemm2(const float* __restrict__ W2,
                                               const float* __restrict__ a_src,
                                               const float* __restrict__ a_dst) {
    __shared__ float Ws[HID * NCLS];
    __shared__ float asv[NCLS], adv[NCLS];
    for (int i = threadIdx.x; i < HID * NCLS; i += blockDim.x) Ws[i] = W2[i];
    if (threadIdx.x < NCLS) { asv[threadIdx.x] = a_src[threadIdx.x]; adv[threadIdx.x] = a_dst[threadIdx.x]; }
    __syncthreads();

    int n = blockIdx.x * blockDim.x + threadIdx.x;
    if (n >= N_NODES) return;

    float acc[NCLS];
#pragma unroll
    for (int c = 0; c < NCLS; c++) acc[c] = 0.f;

    const float4* xr = reinterpret_cast<const float4*>(&g_x2[(size_t)n * HID]);
#pragma unroll
    for (int k4 = 0; k4 < HID / 4; k4++) {
        float4 xv = xr[k4];
        const float* w = &Ws[(k4 * 4) * NCLS];
#pragma unroll
        for (int c = 0; c < NCLS; c++) {
            acc[c] = fmaf(xv.x, w[c], acc[c]);
            acc[c] = fmaf(xv.y, w[NCLS + c], acc[c]);
            acc[c] = fmaf(xv.z, w[2 * NCLS + c], acc[c]);
            acc[c] = fmaf(xv.w, w[3 * NCLS + c], acc[c]);
        }
    }
    float sv = 0.f, dv = 0.f;
#pragma unroll
    for (int c = 0; c < NCLS; c++) {
        g_h2[(size_t)n * NCLS + c] = acc[c];
        sv = fmaf(acc[c], asv[c], sv);
        dv = fmaf(acc[c], adv[c], dv);
    }
    g_s2[n] = sv;
    g_d2[n] = dv;
}

// ---------------- layer-2 aggregate + bias + relu + log_softmax ----------------
__global__ __launch_bounds__(256) void k_agg2(const float* __restrict__ b2,
                                              float* __restrict__ out) {
    int warp = (blockIdx.x * blockDim.x + threadIdx.x) >> 5;
    int lane = threadIdx.x & 31;
    if (warp >= N_NODES) return;
    int n = warp;
    bool has2 = lane < (NCLS - 32);
    int beg = g_rowptr[n], end = g_rowptr[n + 1];
    float dn = g_d2[n];

    float mx = -CUDART_INF_F, den = 0.f, acc0 = 0.f, acc1 = 0.f;

    int base = beg;
    int rem  = end - base;
    int idx  = g_csr_src[base + min(lane, rem - 1)];
    int cnt  = min(rem, 32);
    int j = 0;

    float cs[4], ch0[4], ch1[4];
    load_chunk2(j, idx, cnt, lane, has2, cs, ch0, ch1);
    int cval = cnt - j;

    while (true) {
        int jn = j + 4;
        int idx2 = idx, cnt2 = cnt, base2 = base;
        bool have_next;
        if (jn < cnt) {
            have_next = true;
        } else {
            base2 = base + 32;
            int rem2 = end - base2;
            if (rem2 > 0) {
                idx2 = g_csr_src[base2 + min(lane, rem2 - 1)];
                cnt2 = min(rem2, 32);
                jn = 0;
                have_next = true;
            } else {
                have_next = false;
            }
        }
        float ns[4], nh0[4], nh1[4];
        if (have_next) load_chunk2(jn, idx2, cnt2, lane, has2, ns, nh0, nh1);

        upd2(mx, den, acc0, acc1, cs[0], dn, ch0[0], ch1[0], true);
        upd2(mx, den, acc0, acc1, cs[1], dn, ch0[1], ch1[1], cval > 1);
        upd2(mx, den, acc0, acc1, cs[2], dn, ch0[2], ch1[2], cval > 2);
        upd2(mx, den, acc0, acc1, cs[3], dn, ch0[3], ch1[3], cval > 3);

        if (!have_next) break;
        j = jn; idx = idx2; cnt = cnt2; base = base2;
#pragma unroll
        for (int k = 0; k < 4; k++) { cs[k] = ns[k]; ch0[k] = nh0[k]; ch1[k] = nh1[k]; }
        cval = cnt - j;
    }

    float inv = 1.f / den;
    float v0 = fmaxf(acc0 * inv + b2[lane], 0.f);
    float v1 = has2 ? fmaxf(acc1 * inv + b2[lane + 32], 0.f) : -CUDART_INF_F;

    float m = fmaxf(v0, v1);
#pragma unroll
    for (int o = 16; o > 0; o >>= 1) m = fmaxf(m, __shfl_xor_sync(0xffffffffu, m, o));
    float se = __expf(v0 - m) + (has2 ? __expf(v1 - m) : 0.f);
#pragma unroll
    for (int o = 16; o > 0; o >>= 1) se += __shfl_xor_sync(0xffffffffu, se, o);
    float lse = m + logf(se);

    out[(size_t)n * NCLS + lane] = v0 - lse;
    if (has2) out[(size_t)n * NCLS + lane + 32] = v1 - lse;
}

// ---------------- launch ----------------
extern "C" void kernel_launch(void* const* d_in, const int* in_sizes, int n_in,
                              void* d_out, int out_size) {
    const float* x        = (const float*)d_in[0];
    const int*   edge     = (const int*)  d_in[1];
    const float* W1       = (const float*)d_in[2];
    const float* att_src1 = (const float*)d_in[3];
    const float* att_dst1 = (const float*)d_in[4];
    const float* b1       = (const float*)d_in[5];
    const float* W2       = (const float*)d_in[6];
    const float* att_src2 = (const float*)d_in[7];
    const float* att_dst2 = (const float*)d_in[8];
    const float* b2       = (const float*)d_in[9];
    float* out = (float*)d_out;

    const int* src = edge;
    const int* dst = edge + N_EDGES;

    k_init_deg<<<(N_NODES + 255) / 256, 256>>>();
    k_hist<<<(N_EDGES / 4 + 255) / 256, 256>>>(dst);
    k_bsum<<<NBLK_SCAN, 256>>>();
    k_bscan<<<1, 128>>>();
    k_rowptr<<<NBLK_SCAN, 256>>>();
    k_scatter<<<(N_EDGES / 4 + 255) / 256, 256>>>(src, dst);
    k_scatter_loops<<<(N_NODES + 255) / 256, 256>>>();

    k_gemm1<<<(N_NODES + 255) / 256, 256>>>(x, W1, att_src1, att_dst1);
    k_agg1<<<(N_NODES * 32 + 255) / 256, 256>>>(b1);
    k_gemm2<<<(N_NODES + 255) / 256, 256>>>(W2, att_src2, att_dst2);
    k_agg2<<<(N_NODES * 32 + 255) / 256, 256>>>(b2, out);
}

// round 3
// speedup vs baseline: 1.8518x; 1.3590x over previous
#include <cuda_runtime.h>
#include <math_constants.h>

#define N_NODES 100000
#define N_EDGES 3200000
#define E_TOT   (N_EDGES + N_NODES)   // edges + self loops
#define F_IN    128
#define HID     32
#define NCLS    40
#define NEG_SLOPE 0.2f
#define NBLK_SCAN 98                  // ceil(100000/1024)

// ---------------- scratch (device globals; no allocs allowed) ----------------
__device__ float g_h1[N_NODES * HID];     // x @ W1
__device__ float g_s1[N_NODES];           // h1 . a_src1
__device__ float g_d1[N_NODES];           // h1 . a_dst1
__device__ float g_x2[N_NODES * HID];     // relu(agg1 + b1)
__device__ float g_h2[N_NODES * NCLS];    // x2 @ W2
__device__ float g_s2[N_NODES];
__device__ float g_d2[N_NODES];
__device__ int   g_deg[N_NODES];
__device__ int   g_rowptr[N_NODES + 1];
__device__ int   g_cursor[N_NODES];
__device__ int   g_csr_src[E_TOT];
__device__ int   g_bsum[NBLK_SCAN];
__device__ int   g_boff[NBLK_SCAN];

// ---------------- CSR build ----------------
__global__ void k_init_deg() {
    int i = blockIdx.x * blockDim.x + threadIdx.x;
    if (i < N_NODES) g_deg[i] = 1;  // self loop
}

__global__ void k_hist(const int* __restrict__ dst) {
    int i = blockIdx.x * blockDim.x + threadIdx.x;
    if (i * 4 >= N_EDGES) return;
    int4 d = reinterpret_cast<const int4*>(dst)[i];
    atomicAdd(&g_deg[d.x], 1);
    atomicAdd(&g_deg[d.y], 1);
    atomicAdd(&g_deg[d.z], 1);
    atomicAdd(&g_deg[d.w], 1);
}

__global__ void k_bsum() {
    __shared__ int sh[256];
    int t = threadIdx.x;
    int base = blockIdx.x * 1024 + t * 4;
    int s = 0;
#pragma unroll
    for (int k = 0; k < 4; k++) {
        int i = base + k;
        if (i < N_NODES) s += g_deg[i];
    }
    sh[t] = s;
    __syncthreads();
    for (int off = 128; off > 0; off >>= 1) {
        if (t < off) sh[t] += sh[t + off];
        __syncthreads();
    }
    if (t == 0) g_bsum[blockIdx.x] = sh[0];
}

__global__ void k_bscan() {
    __shared__ int sh[128];
    int t = threadIdx.x;
    int v = (t < NBLK_SCAN) ? g_bsum[t] : 0;
    sh[t] = v;
    __syncthreads();
    for (int off = 1; off < 128; off <<= 1) {
        int u = (t >= off) ? sh[t - off] : 0;
        __syncthreads();
        sh[t] += u;
        __syncthreads();
    }
    if (t < NBLK_SCAN) g_boff[t] = sh[t] - v;  // exclusive
    if (t == 0) g_rowptr[N_NODES] = E_TOT;
}

__global__ void k_rowptr() {
    __shared__ int sh[256];
    int t = threadIdx.x;
    int base = blockIdx.x * 1024 + t * 4;
    int v[4];
    int s = 0;
#pragma unroll
    for (int k = 0; k < 4; k++) {
        int i = base + k;
        v[k] = (i < N_NODES) ? g_deg[i] : 0;
        s += v[k];
    }
    sh[t] = s;
    __syncthreads();
    for (int off = 1; off < 256; off <<= 1) {
        int u = (t >= off) ? sh[t - off] : 0;
        __syncthreads();
        sh[t] += u;
        __syncthreads();
    }
    int run = sh[t] - s + g_boff[blockIdx.x];
#pragma unroll
    for (int k = 0; k < 4; k++) {
        int i = base + k;
        if (i < N_NODES) { g_rowptr[i] = run; g_cursor[i] = run; }
        run += v[k];
    }
}

__global__ void k_scatter(const int* __restrict__ src, const int* __restrict__ dst) {
    int i = blockIdx.x * blockDim.x + threadIdx.x;
    if (i * 4 >= N_EDGES) return;
    int4 s4 = reinterpret_cast<const int4*>(src)[i];
    int4 d4 = reinterpret_cast<const int4*>(dst)[i];
    int p0 = atomicAdd(&g_cursor[d4.x], 1);
    int p1 = atomicAdd(&g_cursor[d4.y], 1);
    int p2 = atomicAdd(&g_cursor[d4.z], 1);
    int p3 = atomicAdd(&g_cursor[d4.w], 1);
    g_csr_src[p0] = s4.x;
    g_csr_src[p1] = s4.y;
    g_csr_src[p2] = s4.z;
    g_csr_src[p3] = s4.w;
}

__global__ void k_scatter_loops() {
    int i = blockIdx.x * blockDim.x + threadIdx.x;
    if (i >= N_NODES) return;
    int p = atomicAdd(&g_cursor[i], 1);
    g_csr_src[p] = i;
}

// ---------------- GEMM1: h1 = x @ W1, s1/d1 attention projections ----------------
__global__ __launch_bounds__(256) void k_gemm1(const float* __restrict__ x,
                                               const float* __restrict__ W1,
                                               const float* __restrict__ a_src,
                                               const float* __restrict__ a_dst) {
    __shared__ float Ws[F_IN * HID];
    __shared__ float asv[HID], adv[HID];
    for (int i = threadIdx.x; i < F_IN * HID; i += blockDim.x) Ws[i] = W1[i];
    if (threadIdx.x < HID) { asv[threadIdx.x] = a_src[threadIdx.x]; adv[threadIdx.x] = a_dst[threadIdx.x]; }
    __syncthreads();

    int n = blockIdx.x * blockDim.x + threadIdx.x;
    if (n >= N_NODES) return;

    float acc[HID];
#pragma unroll
    for (int c = 0; c < HID; c++) acc[c] = 0.f;

    const float4* xr = reinterpret_cast<const float4*>(x + (size_t)n * F_IN);
    const float4* Ws4 = reinterpret_cast<const float4*>(Ws);
#pragma unroll 4
    for (int k4 = 0; k4 < F_IN / 4; k4++) {
        float4 xv = xr[k4];
        int r = (k4 * 4) * (HID / 4);
#pragma unroll
        for (int c4 = 0; c4 < HID / 4; c4++) {
            float4 w0 = Ws4[r + c4];
            float4 w1 = Ws4[r + (HID / 4) + c4];
            float4 w2 = Ws4[r + 2 * (HID / 4) + c4];
            float4 w3 = Ws4[r + 3 * (HID / 4) + c4];
            int c = c4 * 4;
            acc[c+0] = fmaf(xv.x, w0.x, fmaf(xv.y, w1.x, fmaf(xv.z, w2.x, fmaf(xv.w, w3.x, acc[c+0]))));
            acc[c+1] = fmaf(xv.x, w0.y, fmaf(xv.y, w1.y, fmaf(xv.z, w2.y, fmaf(xv.w, w3.y, acc[c+1]))));
            acc[c+2] = fmaf(xv.x, w0.z, fmaf(xv.y, w1.z, fmaf(xv.z, w2.z, fmaf(xv.w, w3.z, acc[c+2]))));
            acc[c+3] = fmaf(xv.x, w0.w, fmaf(xv.y, w1.w, fmaf(xv.z, w2.w, fmaf(xv.w, w3.w, acc[c+3]))));
        }
    }
    float sv = 0.f, dv = 0.f;
#pragma unroll
    for (int c = 0; c < HID; c++) {
        g_h1[(size_t)n * HID + c] = acc[c];
        sv = fmaf(acc[c], asv[c], sv);
        dv = fmaf(acc[c], adv[c], dv);
    }
    g_s1[n] = sv;
    g_d1[n] = dv;
}

// ---------------- layer-1 aggregate: warp per dst, chunk-parallel softmax ----------------
__global__ __launch_bounds__(256) void k_agg1(const float* __restrict__ b1) {
    int warp = (blockIdx.x * blockDim.x + threadIdx.x) >> 5;
    int lane = threadIdx.x & 31;
    if (warp >= N_NODES) return;
    int n = warp;
    int beg = g_rowptr[n], end = g_rowptr[n + 1];
    float dn = g_d1[n];

    float mx = -CUDART_INF_F, den = 0.f, acc = 0.f;

    for (int base = beg; base < end; base += 32) {
        int c = min(32, end - base);
        bool valid = lane < c;
        int idx = g_csr_src[base + (valid ? lane : 0)];  // coalesced
        float sv = g_s1[idx];
        float ev = sv + dn;
        ev = ev > 0.f ? ev : NEG_SLOPE * ev;
        if (!valid) ev = -CUDART_INF_F;

        // warp max of ev
        float cm = ev;
#pragma unroll
        for (int o = 16; o > 0; o >>= 1) cm = fmaxf(cm, __shfl_xor_sync(0xffffffffu, cm, o));
        float nm = fmaxf(mx, cm);
        float sc = __expf(mx - nm);          // 0 on first chunk
        float p  = __expf(ev - nm);          // 0 for invalid lanes

        float ps = p;
#pragma unroll
        for (int o = 16; o > 0; o >>= 1) ps += __shfl_xor_sync(0xffffffffu, ps, o);
        den = den * sc + ps;
        acc = acc * sc;

#pragma unroll 8
        for (int j = 0; j < c; j++) {
            int   ij = __shfl_sync(0xffffffffu, idx, j);
            float pj = __shfl_sync(0xffffffffu, p,   j);
            acc = fmaf(pj, g_h1[ij * HID + lane], acc);
        }
        mx = nm;
    }

    float v = acc / den + b1[lane];
    g_x2[(size_t)n * HID + lane] = fmaxf(v, 0.f);
}

// ---------------- GEMM2: h2 = x2 @ W2, s2/d2 ----------------
__global__ __launch_bounds__(256) void k_gemm2(const float* __restrict__ W2,
                                               const float* __restrict__ a_src,
                                               const float* __restrict__ a_dst) {
    __shared__ float Ws[HID * NCLS];
    __shared__ float asv[NCLS], adv[NCLS];
    for (int i = threadIdx.x; i < HID * NCLS; i += blockDim.x) Ws[i] = W2[i];
    if (threadIdx.x < NCLS) { asv[threadIdx.x] = a_src[threadIdx.x]; adv[threadIdx.x] = a_dst[threadIdx.x]; }
    __syncthreads();

    int n = blockIdx.x * blockDim.x + threadIdx.x;
    if (n >= N_NODES) return;

    float acc[NCLS];
#pragma unroll
    for (int c = 0; c < NCLS; c++) acc[c] = 0.f;

    const float4* xr  = reinterpret_cast<const float4*>(&g_x2[(size_t)n * HID]);
    const float4* Ws4 = reinterpret_cast<const float4*>(Ws);
#pragma unroll
    for (int k4 = 0; k4 < HID / 4; k4++) {
        float4 xv = xr[k4];
        int r = (k4 * 4) * (NCLS / 4);
#pragma unroll
        for (int c4 = 0; c4 < NCLS / 4; c4++) {
            float4 w0 = Ws4[r + c4];
            float4 w1 = Ws4[r + (NCLS / 4) + c4];
            float4 w2 = Ws4[r + 2 * (NCLS / 4) + c4];
            float4 w3 = Ws4[r + 3 * (NCLS / 4) + c4];
            int c = c4 * 4;
            acc[c+0] = fmaf(xv.x, w0.x, fmaf(xv.y, w1.x, fmaf(xv.z, w2.x, fmaf(xv.w, w3.x, acc[c+0]))));
            acc[c+1] = fmaf(xv.x, w0.y, fmaf(xv.y, w1.y, fmaf(xv.z, w2.y, fmaf(xv.w, w3.y, acc[c+1]))));
            acc[c+2] = fmaf(xv.x, w0.z, fmaf(xv.y, w1.z, fmaf(xv.z, w2.z, fmaf(xv.w, w3.z, acc[c+2]))));
            acc[c+3] = fmaf(xv.x, w0.w, fmaf(xv.y, w1.w, fmaf(xv.z, w2.w, fmaf(xv.w, w3.w, acc[c+3]))));
        }
    }
    float sv = 0.f, dv = 0.f;
#pragma unroll
    for (int c = 0; c < NCLS; c++) {
        g_h2[(size_t)n * NCLS + c] = acc[c];
        sv = fmaf(acc[c], asv[c], sv);
        dv = fmaf(acc[c], adv[c], dv);
    }
    g_s2[n] = sv;
    g_d2[n] = dv;
}

// ---------------- layer-2 aggregate + bias + relu + log_softmax ----------------
__global__ __launch_bounds__(256) void k_agg2(const float* __restrict__ b2,
                                              float* __restrict__ out) {
    int warp = (blockIdx.x * blockDim.x + threadIdx.x) >> 5;
    int lane = threadIdx.x & 31;
    if (warp >= N_NODES) return;
    int n = warp;
    bool has2 = lane < (NCLS - 32);
    int beg = g_rowptr[n], end = g_rowptr[n + 1];
    float dn = g_d2[n];

    float mx = -CUDART_INF_F, den = 0.f, acc0 = 0.f, acc1 = 0.f;

    for (int base = beg; base < end; base += 32) {
        int c = min(32, end - base);
        bool valid = lane < c;
        int idx = g_csr_src[base + (valid ? lane : 0)];
        float sv = g_s2[idx];
        float ev = sv + dn;
        ev = ev > 0.f ? ev : NEG_SLOPE * ev;
        if (!valid) ev = -CUDART_INF_F;

        float cm = ev;
#pragma unroll
        for (int o = 16; o > 0; o >>= 1) cm = fmaxf(cm, __shfl_xor_sync(0xffffffffu, cm, o));
        float nm = fmaxf(mx, cm);
        float sc = __expf(mx - nm);
        float p  = __expf(ev - nm);

        float ps = p;
#pragma unroll
        for (int o = 16; o > 0; o >>= 1) ps += __shfl_xor_sync(0xffffffffu, ps, o);
        den = den * sc + ps;
        acc0 = acc0 * sc;
        acc1 = acc1 * sc;

#pragma unroll 8
        for (int j = 0; j < c; j++) {
            int   ij = __shfl_sync(0xffffffffu, idx, j);
            float pj = __shfl_sync(0xffffffffu, p,   j);
            const float* row = &g_h2[(size_t)ij * NCLS];
            acc0 = fmaf(pj, row[lane], acc0);
            if (has2) acc1 = fmaf(pj, row[lane + 32], acc1);
        }
        mx = nm;
    }

    float inv = 1.f / den;
    float v0 = fmaxf(acc0 * inv + b2[lane], 0.f);
    float v1 = has2 ? fmaxf(acc1 * inv + b2[lane + 32], 0.f) : -CUDART_INF_F;

    float m = fmaxf(v0, v1);
#pragma unroll
    for (int o = 16; o > 0; o >>= 1) m = fmaxf(m, __shfl_xor_sync(0xffffffffu, m, o));
    float se = __expf(v0 - m) + (has2 ? __expf(v1 - m) : 0.f);
#pragma unroll
    for (int o = 16; o > 0; o >>= 1) se += __shfl_xor_sync(0xffffffffu, se, o);
    float lse = m + logf(se);

    out[(size_t)n * NCLS + lane] = v0 - lse;
    if (has2) out[(size_t)n * NCLS + lane + 32] = v1 - lse;
}

// ---------------- launch ----------------
extern "C" void kernel_launch(void* const* d_in, const int* in_sizes, int n_in,
                              void* d_out, int out_size) {
    const float* x        = (const float*)d_in[0];
    const int*   edge     = (const int*)  d_in[1];
    const float* W1       = (const float*)d_in[2];
    const float* att_src1 = (const float*)d_in[3];
    const float* att_dst1 = (const float*)d_in[4];
    const float* b1       = (const float*)d_in[5];
    const float* W2       = (const float*)d_in[6];
    const float* att_src2 = (const float*)d_in[7];
    const float* att_dst2 = (const float*)d_in[8];
    const float* b2       = (const float*)d_in[9];
    float* out = (float*)d_out;

    const int* src = edge;
    const int* dst = edge + N_EDGES;

    k_init_deg<<<(N_NODES + 255) / 256, 256>>>();
    k_hist<<<(N_EDGES / 4 + 255) / 256, 256>>>(dst);
    k_bsum<<<NBLK_SCAN, 256>>>();
    k_bscan<<<1, 128>>>();
    k_rowptr<<<NBLK_SCAN, 256>>>();
    k_scatter<<<(N_EDGES / 4 + 255) / 256, 256>>>(src, dst);
    k_scatter_loops<<<(N_NODES + 255) / 256, 256>>>();

    k_gemm1<<<(N_NODES + 255) / 256, 256>>>(x, W1, att_src1, att_dst1);
    k_agg1<<<(N_NODES * 32 + 255) / 256, 256>>>(b1);
    k_gemm2<<<(N_NODES + 255) / 256, 256>>>(W2, att_src2, att_dst2);
    k_agg2<<<(N_NODES * 32 + 255) / 256, 256>>>(b2, out);
}

// round 4
// speedup vs baseline: 1.9008x; 1.0265x over previous
#include <cuda_runtime.h>
#include <math_constants.h>

#define N_NODES 100000
#define N_EDGES 3200000
#define E_TOT   (N_EDGES + N_NODES)   // edges + self loops
#define F_IN    128
#define HID     32
#define NCLS    40
#define NEG_SLOPE 0.2f
#define NBLK_SCAN 98                  // ceil(100000/1024)

// ---------------- scratch (device globals; no allocs allowed) ----------------
__device__ float g_h1[N_NODES * HID];     // x @ W1
__device__ float g_s1[N_NODES];           // h1 . a_src1
__device__ float g_d1[N_NODES];           // h1 . a_dst1
__device__ float g_x2[N_NODES * HID];     // relu(agg1 + b1)
__device__ float g_s2[N_NODES];           // x2 . (W2 a_src2)
__device__ float g_d2[N_NODES];           // x2 . (W2 a_dst2)
__device__ float g_w2s[HID];
__device__ float g_w2d[HID];
__device__ int   g_deg[N_NODES];
__device__ int   g_rowptr[N_NODES + 1];
__device__ int   g_cursor[N_NODES];
__device__ int   g_csr_src[E_TOT];
__device__ int   g_bsum[NBLK_SCAN];
__device__ int   g_boff[NBLK_SCAN];

// ---------------- tiny prep: w2s = W2 @ a_src2, w2d = W2 @ a_dst2 ----------------
__global__ void k_prep(const float* __restrict__ W2,
                       const float* __restrict__ a_src,
                       const float* __restrict__ a_dst) {
    int k = threadIdx.x;           // 0..31 (one per HID row)
    if (k >= HID) return;
    float s = 0.f, d = 0.f;
    const float* row = W2 + k * NCLS;
#pragma unroll
    for (int c = 0; c < NCLS; c++) {
        s = fmaf(row[c], a_src[c], s);
        d = fmaf(row[c], a_dst[c], d);
    }
    g_w2s[k] = s;
    g_w2d[k] = d;
}

// ---------------- CSR build ----------------
__global__ void k_init_deg() {
    int i = blockIdx.x * blockDim.x + threadIdx.x;
    if (i < N_NODES) g_deg[i] = 1;  // self loop
}

__global__ void k_hist(const int* __restrict__ dst) {
    int i = blockIdx.x * blockDim.x + threadIdx.x;
    if (i * 4 >= N_EDGES) return;
    int4 d = reinterpret_cast<const int4*>(dst)[i];
    atomicAdd(&g_deg[d.x], 1);
    atomicAdd(&g_deg[d.y], 1);
    atomicAdd(&g_deg[d.z], 1);
    atomicAdd(&g_deg[d.w], 1);
}

__global__ void k_bsum() {
    __shared__ int sh[256];
    int t = threadIdx.x;
    int base = blockIdx.x * 1024 + t * 4;
    int s = 0;
#pragma unroll
    for (int k = 0; k < 4; k++) {
        int i = base + k;
        if (i < N_NODES) s += g_deg[i];
    }
    sh[t] = s;
    __syncthreads();
    for (int off = 128; off > 0; off >>= 1) {
        if (t < off) sh[t] += sh[t + off];
        __syncthreads();
    }
    if (t == 0) g_bsum[blockIdx.x] = sh[0];
}

__global__ void k_bscan() {
    __shared__ int sh[128];
    int t = threadIdx.x;
    int v = (t < NBLK_SCAN) ? g_bsum[t] : 0;
    sh[t] = v;
    __syncthreads();
    for (int off = 1; off < 128; off <<= 1) {
        int u = (t >= off) ? sh[t - off] : 0;
        __syncthreads();
        sh[t] += u;
        __syncthreads();
    }
    if (t < NBLK_SCAN) g_boff[t] = sh[t] - v;  // exclusive
    if (t == 0) g_rowptr[N_NODES] = E_TOT;
}

__global__ void k_rowptr() {
    __shared__ int sh[256];
    int t = threadIdx.x;
    int base = blockIdx.x * 1024 + t * 4;
    int v[4];
    int s = 0;
#pragma unroll
    for (int k = 0; k < 4; k++) {
        int i = base + k;
        v[k] = (i < N_NODES) ? g_deg[i] : 0;
        s += v[k];
    }
    sh[t] = s;
    __syncthreads();
    for (int off = 1; off < 256; off <<= 1) {
        int u = (t >= off) ? sh[t - off] : 0;
        __syncthreads();
        sh[t] += u;
        __syncthreads();
    }
    int run = sh[t] - s + g_boff[blockIdx.x];
#pragma unroll
    for (int k = 0; k < 4; k++) {
        int i = base + k;
        if (i < N_NODES) { g_rowptr[i] = run; g_cursor[i] = run; }
        run += v[k];
    }
}

__global__ void k_scatter(const int* __restrict__ src, const int* __restrict__ dst) {
    int i = blockIdx.x * blockDim.x + threadIdx.x;
    if (i * 4 >= N_EDGES) return;
    int4 s4 = reinterpret_cast<const int4*>(src)[i];
    int4 d4 = reinterpret_cast<const int4*>(dst)[i];
    int p0 = atomicAdd(&g_cursor[d4.x], 1);
    int p1 = atomicAdd(&g_cursor[d4.y], 1);
    int p2 = atomicAdd(&g_cursor[d4.z], 1);
    int p3 = atomicAdd(&g_cursor[d4.w], 1);
    g_csr_src[p0] = s4.x;
    g_csr_src[p1] = s4.y;
    g_csr_src[p2] = s4.z;
    g_csr_src[p3] = s4.w;
}

__global__ void k_scatter_loops() {
    int i = blockIdx.x * blockDim.x + threadIdx.x;
    if (i >= N_NODES) return;
    int p = atomicAdd(&g_cursor[i], 1);
    g_csr_src[p] = i;
}

// ---------------- GEMM1: h1 = x @ W1, s1/d1 attention projections ----------------
__global__ __launch_bounds__(256) void k_gemm1(const float* __restrict__ x,
                                               const float* __restrict__ W1,
                                               const float* __restrict__ a_src,
                                               const float* __restrict__ a_dst) {
    __shared__ float Ws[F_IN * HID];
    __shared__ float asv[HID], adv[HID];
    for (int i = threadIdx.x; i < F_IN * HID; i += blockDim.x) Ws[i] = W1[i];
    if (threadIdx.x < HID) { asv[threadIdx.x] = a_src[threadIdx.x]; adv[threadIdx.x] = a_dst[threadIdx.x]; }
    __syncthreads();

    int n = blockIdx.x * blockDim.x + threadIdx.x;
    if (n >= N_NODES) return;

    float acc[HID];
#pragma unroll
    for (int c = 0; c < HID; c++) acc[c] = 0.f;

    const float4* xr = reinterpret_cast<const float4*>(x + (size_t)n * F_IN);
    const float4* Ws4 = reinterpret_cast<const float4*>(Ws);
#pragma unroll 4
    for (int k4 = 0; k4 < F_IN / 4; k4++) {
        float4 xv = xr[k4];
        int r = (k4 * 4) * (HID / 4);
#pragma unroll
        for (int c4 = 0; c4 < HID / 4; c4++) {
            float4 w0 = Ws4[r + c4];
            float4 w1 = Ws4[r + (HID / 4) + c4];
            float4 w2 = Ws4[r + 2 * (HID / 4) + c4];
            float4 w3 = Ws4[r + 3 * (HID / 4) + c4];
            int c = c4 * 4;
            acc[c+0] = fmaf(xv.x, w0.x, fmaf(xv.y, w1.x, fmaf(xv.z, w2.x, fmaf(xv.w, w3.x, acc[c+0]))));
            acc[c+1] = fmaf(xv.x, w0.y, fmaf(xv.y, w1.y, fmaf(xv.z, w2.y, fmaf(xv.w, w3.y, acc[c+1]))));
            acc[c+2] = fmaf(xv.x, w0.z, fmaf(xv.y, w1.z, fmaf(xv.z, w2.z, fmaf(xv.w, w3.z, acc[c+2]))));
            acc[c+3] = fmaf(xv.x, w0.w, fmaf(xv.y, w1.w, fmaf(xv.z, w2.w, fmaf(xv.w, w3.w, acc[c+3]))));
        }
    }
    float sv = 0.f, dv = 0.f;
#pragma unroll
    for (int c = 0; c < HID; c++) {
        g_h1[(size_t)n * HID + c] = acc[c];
        sv = fmaf(acc[c], asv[c], sv);
        dv = fmaf(acc[c], adv[c], dv);
    }
    g_s1[n] = sv;
    g_d1[n] = dv;
}

// ---- layer-1 aggregate: warp per dst, chunk-parallel softmax; epilogue emits s2/d2 ----
__global__ __launch_bounds__(256) void k_agg1(const float* __restrict__ b1) {
    int warp = (blockIdx.x * blockDim.x + threadIdx.x) >> 5;
    int lane = threadIdx.x & 31;
    if (warp >= N_NODES) return;
    int n = warp;
    int beg = g_rowptr[n], end = g_rowptr[n + 1];
    float dn = g_d1[n];

    float mx = -CUDART_INF_F, den = 0.f, acc = 0.f;

    for (int base = beg; base < end; base += 32) {
        int c = min(32, end - base);
        bool valid = lane < c;
        int idx = g_csr_src[base + (valid ? lane : 0)];  // coalesced
        float sv = g_s1[idx];
        float ev = sv + dn;
        ev = ev > 0.f ? ev : NEG_SLOPE * ev;
        if (!valid) ev = -CUDART_INF_F;

        float cm = ev;
#pragma unroll
        for (int o = 16; o > 0; o >>= 1) cm = fmaxf(cm, __shfl_xor_sync(0xffffffffu, cm, o));
        float nm = fmaxf(mx, cm);
        float sc = __expf(mx - nm);
        float p  = __expf(ev - nm);

        float ps = p;
#pragma unroll
        for (int o = 16; o > 0; o >>= 1) ps += __shfl_xor_sync(0xffffffffu, ps, o);
        den = den * sc + ps;
        acc = acc * sc;

#pragma unroll 8
        for (int j = 0; j < c; j++) {
            int   ij = __shfl_sync(0xffffffffu, idx, j);
            float pj = __shfl_sync(0xffffffffu, p,   j);
            acc = fmaf(pj, g_h1[ij * HID + lane], acc);
        }
        mx = nm;
    }

    float v = fmaxf(acc / den + b1[lane], 0.f);
    g_x2[(size_t)n * HID + lane] = v;

    // epilogue: s2/d2 projections for layer 2 (gemm2 fused away)
    float sp = v * g_w2s[lane];
    float dp = v * g_w2d[lane];
#pragma unroll
    for (int o = 16; o > 0; o >>= 1) {
        sp += __shfl_xor_sync(0xffffffffu, sp, o);
        dp += __shfl_xor_sync(0xffffffffu, dp, o);
    }
    if (lane == 0) { g_s2[n] = sp; g_d2[n] = dp; }
}

// ---- layer-2: aggregate x2 (one 128B line/edge), epilogue W2 GEMM + bias + relu + log_softmax ----
__global__ __launch_bounds__(256) void k_agg2(const float* __restrict__ W2,
                                              const float* __restrict__ b2,
                                              float* __restrict__ out) {
    __shared__ float W2s[HID * NCLS];   // 5120 B
    for (int i = threadIdx.x; i < HID * NCLS; i += blockDim.x) W2s[i] = W2[i];
    __syncthreads();

    int warp = (blockIdx.x * blockDim.x + threadIdx.x) >> 5;
    int lane = threadIdx.x & 31;
    if (warp >= N_NODES) return;
    int n = warp;
    bool has2 = lane < (NCLS - 32);
    int beg = g_rowptr[n], end = g_rowptr[n + 1];
    float dn = g_d2[n];

    float mx = -CUDART_INF_F, den = 0.f, aggx = 0.f;

    for (int base = beg; base < end; base += 32) {
        int c = min(32, end - base);
        bool valid = lane < c;
        int idx = g_csr_src[base + (valid ? lane : 0)];
        float sv = g_s2[idx];
        float ev = sv + dn;
        ev = ev > 0.f ? ev : NEG_SLOPE * ev;
        if (!valid) ev = -CUDART_INF_F;

        float cm = ev;
#pragma unroll
        for (int o = 16; o > 0; o >>= 1) cm = fmaxf(cm, __shfl_xor_sync(0xffffffffu, cm, o));
        float nm = fmaxf(mx, cm);
        float sc = __expf(mx - nm);
        float p  = __expf(ev - nm);

        float ps = p;
#pragma unroll
        for (int o = 16; o > 0; o >>= 1) ps += __shfl_xor_sync(0xffffffffu, ps, o);
        den = den * sc + ps;
        aggx = aggx * sc;

#pragma unroll 8
        for (int j = 0; j < c; j++) {
            int   ij = __shfl_sync(0xffffffffu, idx, j);
            float pj = __shfl_sync(0xffffffffu, p,   j);
            aggx = fmaf(pj, g_x2[ij * HID + lane], aggx);   // 128B aligned row
        }
        mx = nm;
    }

    aggx = aggx / den;   // aggregated x2 in lane = channel

    // epilogue GEMM: h_out[c] = sum_k aggx_k * W2[k][c] + b2[c]
    float acc0 = b2[lane];
    float acc1 = has2 ? b2[lane + 32] : 0.f;
#pragma unroll
    for (int k = 0; k < HID; k++) {
        float xk = __shfl_sync(0xffffffffu, aggx, k);
        acc0 = fmaf(xk, W2s[k * NCLS + lane], acc0);
        if (has2) acc1 = fmaf(xk, W2s[k * NCLS + lane + 32], acc1);
    }
    float v0 = fmaxf(acc0, 0.f);
    float v1 = has2 ? fmaxf(acc1, 0.f) : -CUDART_INF_F;

    float m = fmaxf(v0, v1);
#pragma unroll
    for (int o = 16; o > 0; o >>= 1) m = fmaxf(m, __shfl_xor_sync(0xffffffffu, m, o));
    float se = __expf(v0 - m) + (has2 ? __expf(v1 - m) : 0.f);
#pragma unroll
    for (int o = 16; o > 0; o >>= 1) se += __shfl_xor_sync(0xffffffffu, se, o);
    float lse = m + logf(se);

    out[(size_t)n * NCLS + lane] = v0 - lse;
    if (has2) out[(size_t)n * NCLS + lane + 32] = v1 - lse;
}

// ---------------- launch ----------------
extern "C" void kernel_launch(void* const* d_in, const int* in_sizes, int n_in,
                              void* d_out, int out_size) {
    const float* x        = (const float*)d_in[0];
    const int*   edge     = (const int*)  d_in[1];
    const float* W1       = (const float*)d_in[2];
    const float* att_src1 = (const float*)d_in[3];
    const float* att_dst1 = (const float*)d_in[4];
    const float* b1       = (const float*)d_in[5];
    const float* W2       = (const float*)d_in[6];
    const float* att_src2 = (const float*)d_in[7];
    const float* att_dst2 = (const float*)d_in[8];
    const float* b2       = (const float*)d_in[9];
    float* out = (float*)d_out;

    const int* src = edge;
    const int* dst = edge + N_EDGES;

    k_prep<<<1, 32>>>(W2, att_src2, att_dst2);
    k_init_deg<<<(N_NODES + 255) / 256, 256>>>();
    k_hist<<<(N_EDGES / 4 + 255) / 256, 256>>>(dst);
    k_bsum<<<NBLK_SCAN, 256>>>();
    k_bscan<<<1, 128>>>();
    k_rowptr<<<NBLK_SCAN, 256>>>();
    k_scatter<<<(N_EDGES / 4 + 255) / 256, 256>>>(src, dst);
    k_scatter_loops<<<(N_NODES + 255) / 256, 256>>>();

    k_gemm1<<<(N_NODES + 255) / 256, 256>>>(x, W1, att_src1, att_dst1);
    k_agg1<<<(N_NODES * 32 + 255) / 256, 256>>>(b1);
    k_agg2<<<(N_NODES * 32 + 255) / 256, 256>>>(W2, b2, out);
}

// round 5
// speedup vs baseline: 2.0962x; 1.1028x over previous
#include <cuda_runtime.h>
#include <math_constants.h>

#define N_NODES 100000
#define N_EDGES 3200000
#define E_TOT   (N_EDGES + N_NODES)   // edges + self loops
#define F_IN    128
#define HID     32
#define NCLS    40
#define NEG_SLOPE 0.2f
#define NBLK_SCAN 98                  // ceil(100000/1024)

// ---------------- scratch (device globals; no allocs allowed) ----------------
__device__ float g_h1[N_NODES * HID];     // x @ W1
__device__ float g_s1[N_NODES];           // h1 . a_src1
__device__ float g_d1[N_NODES];           // h1 . a_dst1
__device__ float g_x2[N_NODES * HID];     // relu(agg1 + b1)
__device__ float g_s2[N_NODES];           // x2 . (W2 a_src2)
__device__ float g_d2[N_NODES];           // x2 . (W2 a_dst2)
__device__ float g_w2s[HID];
__device__ float g_w2d[HID];
__device__ int   g_deg[N_NODES];
__device__ int   g_rowptr[N_NODES + 1];
__device__ int   g_cursor[N_NODES];
__device__ int   g_csr_src[E_TOT];
__device__ int   g_bsum[NBLK_SCAN];
__device__ int   g_boff[NBLK_SCAN];

// ---------------- tiny prep: w2s = W2 @ a_src2, w2d = W2 @ a_dst2 ----------------
__global__ void k_prep(const float* __restrict__ W2,
                       const float* __restrict__ a_src,
                       const float* __restrict__ a_dst) {
    int k = threadIdx.x;           // 0..31 (one per HID row)
    if (k >= HID) return;
    float s = 0.f, d = 0.f;
    const float* row = W2 + k * NCLS;
#pragma unroll
    for (int c = 0; c < NCLS; c++) {
        s = fmaf(row[c], a_src[c], s);
        d = fmaf(row[c], a_dst[c], d);
    }
    g_w2s[k] = s;
    g_w2d[k] = d;
}

// ---------------- CSR build ----------------
__global__ void k_init_deg() {
    int i = blockIdx.x * blockDim.x + threadIdx.x;
    if (i < N_NODES) g_deg[i] = 1;  // self loop
}

__global__ void k_hist(const int* __restrict__ dst) {
    int i = blockIdx.x * blockDim.x + threadIdx.x;
    if (i * 4 >= N_EDGES) return;
    int4 d = reinterpret_cast<const int4*>(dst)[i];
    atomicAdd(&g_deg[d.x], 1);
    atomicAdd(&g_deg[d.y], 1);
    atomicAdd(&g_deg[d.z], 1);
    atomicAdd(&g_deg[d.w], 1);
}

__global__ void k_bsum() {
    __shared__ int sh[256];
    int t = threadIdx.x;
    int base = blockIdx.x * 1024 + t * 4;
    int s = 0;
#pragma unroll
    for (int k = 0; k < 4; k++) {
        int i = base + k;
        if (i < N_NODES) s += g_deg[i];
    }
    sh[t] = s;
    __syncthreads();
    for (int off = 128; off > 0; off >>= 1) {
        if (t < off) sh[t] += sh[t + off];
        __syncthreads();
    }
    if (t == 0) g_bsum[blockIdx.x] = sh[0];
}

__global__ void k_bscan() {
    __shared__ int sh[128];
    int t = threadIdx.x;
    int v = (t < NBLK_SCAN) ? g_bsum[t] : 0;
    sh[t] = v;
    __syncthreads();
    for (int off = 1; off < 128; off <<= 1) {
        int u = (t >= off) ? sh[t - off] : 0;
        __syncthreads();
        sh[t] += u;
        __syncthreads();
    }
    if (t < NBLK_SCAN) g_boff[t] = sh[t] - v;  // exclusive
    if (t == 0) g_rowptr[N_NODES] = E_TOT;
}

// per-block exclusive scan -> rowptr; also place self-loop at segment head
__global__ void k_rowptr() {
    __shared__ int sh[256];
    int t = threadIdx.x;
    int base = blockIdx.x * 1024 + t * 4;
    int v[4];
    int s = 0;
#pragma unroll
    for (int k = 0; k < 4; k++) {
        int i = base + k;
        v[k] = (i < N_NODES) ? g_deg[i] : 0;
        s += v[k];
    }
    sh[t] = s;
    __syncthreads();
    for (int off = 1; off < 256; off <<= 1) {
        int u = (t >= off) ? sh[t - off] : 0;
        __syncthreads();
        sh[t] += u;
        __syncthreads();
    }
    int run = sh[t] - s + g_boff[blockIdx.x];
#pragma unroll
    for (int k = 0; k < 4; k++) {
        int i = base + k;
        if (i < N_NODES) {
            g_rowptr[i] = run;
            g_csr_src[run] = i;       // self loop at head of segment
            g_cursor[i] = run + 1;    // edges fill after it
        }
        run += v[k];
    }
}

__global__ void k_scatter(const int* __restrict__ src, const int* __restrict__ dst) {
    int i = blockIdx.x * blockDim.x + threadIdx.x;
    if (i * 4 >= N_EDGES) return;
    int4 s4 = reinterpret_cast<const int4*>(src)[i];
    int4 d4 = reinterpret_cast<const int4*>(dst)[i];
    int p0 = atomicAdd(&g_cursor[d4.x], 1);
    int p1 = atomicAdd(&g_cursor[d4.y], 1);
    int p2 = atomicAdd(&g_cursor[d4.z], 1);
    int p3 = atomicAdd(&g_cursor[d4.w], 1);
    g_csr_src[p0] = s4.x;
    g_csr_src[p1] = s4.y;
    g_csr_src[p2] = s4.z;
    g_csr_src[p3] = s4.w;
}

// ---------------- GEMM1: h1 = x @ W1, s1/d1 attention projections ----------------
__global__ __launch_bounds__(256) void k_gemm1(const float* __restrict__ x,
                                               const float* __restrict__ W1,
                                               const float* __restrict__ a_src,
                                               const float* __restrict__ a_dst) {
    __shared__ float Ws[F_IN * HID];
    __shared__ float asv[HID], adv[HID];
    for (int i = threadIdx.x; i < F_IN * HID; i += blockDim.x) Ws[i] = W1[i];
    if (threadIdx.x < HID) { asv[threadIdx.x] = a_src[threadIdx.x]; adv[threadIdx.x] = a_dst[threadIdx.x]; }
    __syncthreads();

    int n = blockIdx.x * blockDim.x + threadIdx.x;
    if (n >= N_NODES) return;

    float acc[HID];
#pragma unroll
    for (int c = 0; c < HID; c++) acc[c] = 0.f;

    const float4* xr = reinterpret_cast<const float4*>(x + (size_t)n * F_IN);
    const float4* Ws4 = reinterpret_cast<const float4*>(Ws);
#pragma unroll 4
    for (int k4 = 0; k4 < F_IN / 4; k4++) {
        float4 xv = xr[k4];
        int r = (k4 * 4) * (HID / 4);
#pragma unroll
        for (int c4 = 0; c4 < HID / 4; c4++) {
            float4 w0 = Ws4[r + c4];
            float4 w1 = Ws4[r + (HID / 4) + c4];
            float4 w2 = Ws4[r + 2 * (HID / 4) + c4];
            float4 w3 = Ws4[r + 3 * (HID / 4) + c4];
            int c = c4 * 4;
            acc[c+0] = fmaf(xv.x, w0.x, fmaf(xv.y, w1.x, fmaf(xv.z, w2.x, fmaf(xv.w, w3.x, acc[c+0]))));
            acc[c+1] = fmaf(xv.x, w0.y, fmaf(xv.y, w1.y, fmaf(xv.z, w2.y, fmaf(xv.w, w3.y, acc[c+1]))));
            acc[c+2] = fmaf(xv.x, w0.z, fmaf(xv.y, w1.z, fmaf(xv.z, w2.z, fmaf(xv.w, w3.z, acc[c+2]))));
            acc[c+3] = fmaf(xv.x, w0.w, fmaf(xv.y, w1.w, fmaf(xv.z, w2.w, fmaf(xv.w, w3.w, acc[c+3]))));
        }
    }
    float sv = 0.f, dv = 0.f;
#pragma unroll
    for (int c = 0; c < HID; c++) {
        g_h1[(size_t)n * HID + c] = acc[c];
        sv = fmaf(acc[c], asv[c], sv);
        dv = fmaf(acc[c], adv[c], dv);
    }
    g_s1[n] = sv;
    g_d1[n] = dv;
}

// ---- layer-1 aggregate: warp/dst, chunk softmax, smem (p,idx) broadcast ----
__global__ __launch_bounds__(256) void k_agg1(const float* __restrict__ b1) {
    __shared__ float2 shp[8][2][32];   // [warp][buf][slot]
    int tid = threadIdx.x;
    int wib = tid >> 5;
    int lane = tid & 31;
    int n = (blockIdx.x * blockDim.x + tid) >> 5;
    if (n >= N_NODES) return;
    int beg = g_rowptr[n], end = g_rowptr[n + 1];
    float dn = g_d1[n];

    float mx = -CUDART_INF_F, den = 0.f, acc0 = 0.f, acc1 = 0.f;
    int buf = 0;

    for (int base = beg; base < end; base += 32, buf ^= 1) {
        int c = min(32, end - base);
        bool valid = lane < c;
        int idx = g_csr_src[base + (valid ? lane : 0)];  // coalesced
        float sv = g_s1[idx];
        float ev = sv + dn;
        ev = ev > 0.f ? ev : NEG_SLOPE * ev;
        if (!valid) ev = -CUDART_INF_F;

        float cm = ev;
#pragma unroll
        for (int o = 16; o > 0; o >>= 1) cm = fmaxf(cm, __shfl_xor_sync(0xffffffffu, cm, o));
        float nm = fmaxf(mx, cm);
        float sc = __expf(mx - nm);
        float p  = __expf(ev - nm);

        float ps = p;
#pragma unroll
        for (int o = 16; o > 0; o >>= 1) ps += __shfl_xor_sync(0xffffffffu, ps, o);
        den = den * sc + ps;
        acc0 *= sc;
        acc1 *= sc;

        shp[wib][buf][lane] = make_float2(p, __int_as_float(idx * HID));
        __syncwarp();
        const float2* pr = shp[wib][buf];
        int j = 0;
        for (; j + 4 <= c; j += 4) {
            float2 q0 = pr[j], q1 = pr[j+1], q2 = pr[j+2], q3 = pr[j+3];
            acc0 = fmaf(q0.x, g_h1[__float_as_int(q0.y) + lane], acc0);
            acc1 = fmaf(q1.x, g_h1[__float_as_int(q1.y) + lane], acc1);
            acc0 = fmaf(q2.x, g_h1[__float_as_int(q2.y) + lane], acc0);
            acc1 = fmaf(q3.x, g_h1[__float_as_int(q3.y) + lane], acc1);
        }
        for (; j < c; j++) {
            float2 q = pr[j];
            acc0 = fmaf(q.x, g_h1[__float_as_int(q.y) + lane], acc0);
        }
        mx = nm;
    }

    float v = fmaxf((acc0 + acc1) / den + b1[lane], 0.f);
    g_x2[(size_t)n * HID + lane] = v;

    // epilogue: s2/d2 projections for layer 2 (gemm2 fused away)
    float sp = v * g_w2s[lane];
    float dp = v * g_w2d[lane];
#pragma unroll
    for (int o = 16; o > 0; o >>= 1) {
        sp += __shfl_xor_sync(0xffffffffu, sp, o);
        dp += __shfl_xor_sync(0xffffffffu, dp, o);
    }
    if (lane == 0) { g_s2[n] = sp; g_d2[n] = dp; }
}

// ---- layer-2: aggregate x2, epilogue W2 GEMM + bias + relu + log_softmax ----
__global__ __launch_bounds__(256) void k_agg2(const float* __restrict__ W2,
                                              const float* __restrict__ b2,
                                              float* __restrict__ out) {
    __shared__ float W2s[HID * NCLS];   // 5120 B
    __shared__ float2 shp[8][2][32];
    for (int i = threadIdx.x; i < HID * NCLS; i += blockDim.x) W2s[i] = W2[i];
    __syncthreads();

    int tid = threadIdx.x;
    int wib = tid >> 5;
    int lane = tid & 31;
    int n = (blockIdx.x * blockDim.x + tid) >> 5;
    if (n >= N_NODES) return;
    bool has2 = lane < (NCLS - 32);
    int beg = g_rowptr[n], end = g_rowptr[n + 1];
    float dn = g_d2[n];

    float mx = -CUDART_INF_F, den = 0.f, acc0 = 0.f, acc1 = 0.f;
    int buf = 0;

    for (int base = beg; base < end; base += 32, buf ^= 1) {
        int c = min(32, end - base);
        bool valid = lane < c;
        int idx = g_csr_src[base + (valid ? lane : 0)];
        float sv = g_s2[idx];
        float ev = sv + dn;
        ev = ev > 0.f ? ev : NEG_SLOPE * ev;
        if (!valid) ev = -CUDART_INF_F;

        float cm = ev;
#pragma unroll
        for (int o = 16; o > 0; o >>= 1) cm = fmaxf(cm, __shfl_xor_sync(0xffffffffu, cm, o));
        float nm = fmaxf(mx, cm);
        float sc = __expf(mx - nm);
        float p  = __expf(ev - nm);

        float ps = p;
#pragma unroll
        for (int o = 16; o > 0; o >>= 1) ps += __shfl_xor_sync(0xffffffffu, ps, o);
        den = den * sc + ps;
        acc0 *= sc;
        acc1 *= sc;

        shp[wib][buf][lane] = make_float2(p, __int_as_float(idx * HID));
        __syncwarp();
        const float2* pr = shp[wib][buf];
        int j = 0;
        for (; j + 4 <= c; j += 4) {
            float2 q0 = pr[j], q1 = pr[j+1], q2 = pr[j+2], q3 = pr[j+3];
            acc0 = fmaf(q0.x, g_x2[__float_as_int(q0.y) + lane], acc0);
            acc1 = fmaf(q1.x, g_x2[__float_as_int(q1.y) + lane], acc1);
            acc0 = fmaf(q2.x, g_x2[__float_as_int(q2.y) + lane], acc0);
            acc1 = fmaf(q3.x, g_x2[__float_as_int(q3.y) + lane], acc1);
        }
        for (; j < c; j++) {
            float2 q = pr[j];
            acc0 = fmaf(q.x, g_x2[__float_as_int(q.y) + lane], acc0);
        }
        mx = nm;
    }

    float aggx = (acc0 + acc1) / den;   // aggregated x2, lane = channel

    // epilogue GEMM: h_out[c] = sum_k aggx_k * W2[k][c] + b2[c]
    float o0 = b2[lane];
    float o1 = has2 ? b2[lane + 32] : 0.f;
#pragma unroll
    for (int k = 0; k < HID; k++) {
        float xk = __shfl_sync(0xffffffffu, aggx, k);
        o0 = fmaf(xk, W2s[k * NCLS + lane], o0);
        if (has2) o1 = fmaf(xk, W2s[k * NCLS + lane + 32], o1);
    }
    float v0 = fmaxf(o0, 0.f);
    float v1 = has2 ? fmaxf(o1, 0.f) : -CUDART_INF_F;

    float m = fmaxf(v0, v1);
#pragma unroll
    for (int o = 16; o > 0; o >>= 1) m = fmaxf(m, __shfl_xor_sync(0xffffffffu, m, o));
    float se = __expf(v0 - m) + (has2 ? __expf(v1 - m) : 0.f);
#pragma unroll
    for (int o = 16; o > 0; o >>= 1) se += __shfl_xor_sync(0xffffffffu, se, o);
    float lse = m + logf(se);

    out[(size_t)n * NCLS + lane] = v0 - lse;
    if (has2) out[(size_t)n * NCLS + lane + 32] = v1 - lse;
}

// ---------------- launch ----------------
extern "C" void kernel_launch(void* const* d_in, const int* in_sizes, int n_in,
                              void* d_out, int out_size) {
    const float* x        = (const float*)d_in[0];
    const int*   edge     = (const int*)  d_in[1];
    const float* W1       = (const float*)d_in[2];
    const float* att_src1 = (const float*)d_in[3];
    const float* att_dst1 = (const float*)d_in[4];
    const float* b1       = (const float*)d_in[5];
    const float* W2       = (const float*)d_in[6];
    const float* att_src2 = (const float*)d_in[7];
    const float* att_dst2 = (const float*)d_in[8];
    const float* b2       = (const float*)d_in[9];
    float* out = (float*)d_out;

    const int* src = edge;
    const int* dst = edge + N_EDGES;

    // lazily created side stream + events (created on the non-captured
    // correctness call; reused during capture — fork/join pattern)
    static cudaStream_t s2 = nullptr;
    static cudaEvent_t evFork = nullptr, evJoin = nullptr;
    if (!s2) {
        cudaStreamCreateWithFlags(&s2, cudaStreamNonBlocking);
        cudaEventCreateWithFlags(&evFork, cudaEventDisableTiming);
        cudaEventCreateWithFlags(&evJoin, cudaEventDisableTiming);
    }

    // fork: gemm1 + prep are independent of the CSR build
    cudaEventRecord(evFork, 0);
    cudaStreamWaitEvent(s2, evFork, 0);
    k_prep<<<1, 32, 0, s2>>>(W2, att_src2, att_dst2);
    k_gemm1<<<(N_NODES + 255) / 256, 256, 0, s2>>>(x, W1, att_src1, att_dst1);
    cudaEventRecord(evJoin, s2);

    // main stream: CSR build
    k_init_deg<<<(N_NODES + 255) / 256, 256>>>();
    k_hist<<<(N_EDGES / 4 + 255) / 256, 256>>>(dst);
    k_bsum<<<NBLK_SCAN, 256>>>();
    k_bscan<<<1, 128>>>();
    k_rowptr<<<NBLK_SCAN, 256>>>();
    k_scatter<<<(N_EDGES / 4 + 255) / 256, 256>>>(src, dst);

    // join, then aggregates
    cudaStreamWaitEvent(0, evJoin, 0);
    k_agg1<<<(N_NODES * 32 + 255) / 256, 256>>>(b1);
    k_agg2<<<(N_NODES * 32 + 255) / 256, 256>>>(W2, b2, out);
}

// round 6
// speedup vs baseline: 2.1403x; 1.0210x over previous
#include <cuda_runtime.h>
#include <math_constants.h>

#define N_NODES 100000
#define N_EDGES 3200000
#define E_TOT   (N_EDGES + N_NODES)   // edges + self loops
#define F_IN    128
#define HID     32
#define NCLS    40
#define NEG_SLOPE 0.2f
#define NBLK_SCAN 98                  // ceil(100000/1024)
#define NBUCKET 4
#define NQUAD (N_EDGES / 4)           // 800000 quads of edges

// ---------------- scratch (device globals; no allocs allowed) ----------------
__device__ float g_h1[N_NODES * HID];     // x @ W1
__device__ float g_s1[N_NODES];           // h1 . a_src1
__device__ float g_d1[N_NODES];           // h1 . a_dst1
__device__ float g_x2[N_NODES * HID];     // relu(agg1 + b1)
__device__ float g_s2[N_NODES];           // x2 . (W2 a_src2)
__device__ float g_d2[N_NODES];           // x2 . (W2 a_dst2)
__device__ float g_w2s[HID];
__device__ float g_w2d[HID];
__device__ int   g_deg[NBUCKET][N_NODES];     // bucketed degree counters
__device__ int   g_cursor[NBUCKET][N_NODES];  // bucketed scatter cursors
__device__ int   g_rowptr[N_NODES + 1];
__device__ int   g_csr_src[E_TOT];
__device__ int   g_bsum[NBLK_SCAN];
__device__ int   g_ready;                     // scan arrive counter

// ---------------- tiny prep: w2s = W2 @ a_src2, w2d = W2 @ a_dst2 ----------------
__global__ void k_prep(const float* __restrict__ W2,
                       const float* __restrict__ a_src,
                       const float* __restrict__ a_dst) {
    int k = threadIdx.x;
    if (k >= HID) return;
    float s = 0.f, d = 0.f;
    const float* row = W2 + k * NCLS;
#pragma unroll
    for (int c = 0; c < NCLS; c++) {
        s = fmaf(row[c], a_src[c], s);
        d = fmaf(row[c], a_dst[c], d);
    }
    g_w2s[k] = s;
    g_w2d[k] = d;
}

// ---------------- CSR build ----------------
// 4 edges per thread; bucket = quad_index & 3
__global__ void k_hist(const int* __restrict__ dst) {
    int i = blockIdx.x * blockDim.x + threadIdx.x;
    if (i >= NQUAD) return;
    int4 d = reinterpret_cast<const int4*>(dst)[i];
    int* deg = g_deg[i & (NBUCKET - 1)];
    atomicAdd(&deg[d.x], 1);
    atomicAdd(&deg[d.y], 1);
    atomicAdd(&deg[d.z], 1);
    atomicAdd(&deg[d.w], 1);
}

// fused scan: block sums -> grid sync (atomic arrive + spin) -> rowptr/cursors/self-loops
__global__ __launch_bounds__(256) void k_scan() {
    __shared__ int sh[256];
    __shared__ int blk_off;
    int t = threadIdx.x;
    int base = blockIdx.x * 1024 + t * 4;

    // per-thread degs (self loop contributes +1 per node)
    int v[4];
    int s = 0;
#pragma unroll
    for (int k = 0; k < 4; k++) {
        int i = base + k;
        int d = 0;
        if (i < N_NODES) {
            d = 1 + g_deg[0][i] + g_deg[1][i] + g_deg[2][i] + g_deg[3][i];
        }
        v[k] = d;
        s += d;
    }
    sh[t] = s;
    __syncthreads();
    // inclusive scan of per-thread sums
    for (int off = 1; off < 256; off <<= 1) {
        int u = (t >= off) ? sh[t - off] : 0;
        __syncthreads();
        sh[t] += u;
        __syncthreads();
    }
    int thr_excl = sh[t] - s;
    int blk_total = sh[255];

    // publish block total, arrive, spin until all arrived
    if (t == 0) {
        g_bsum[blockIdx.x] = blk_total;
        __threadfence();
        atomicAdd(&g_ready, 1);
        while (atomicAdd(&g_ready, 0) < NBLK_SCAN) { }
        // exclusive prefix of block sums
        int off = 0;
        for (int b = 0; b < (int)blockIdx.x; b++) off += g_bsum[b];
        blk_off = off;
    }
    __syncthreads();

    int run = blk_off + thr_excl;
#pragma unroll
    for (int k = 0; k < 4; k++) {
        int i = base + k;
        if (i < N_NODES) {
            g_rowptr[i] = run;
            g_csr_src[run] = i;                 // self loop at head
            int c0 = run + 1;
            g_cursor[0][i] = c0;
            int c1 = c0 + g_deg[0][i];
            g_cursor[1][i] = c1;
            int c2 = c1 + g_deg[1][i];
            g_cursor[2][i] = c2;
            g_cursor[3][i] = c2 + g_deg[2][i];
        }
        run += v[k];
    }
    if (blockIdx.x == NBLK_SCAN - 1 && t == 255) g_rowptr[N_NODES] = E_TOT;
}

__global__ void k_scatter(const int* __restrict__ src, const int* __restrict__ dst) {
    int i = blockIdx.x * blockDim.x + threadIdx.x;
    if (i >= NQUAD) return;
    int4 s4 = reinterpret_cast<const int4*>(src)[i];
    int4 d4 = reinterpret_cast<const int4*>(dst)[i];
    int* cur = g_cursor[i & (NBUCKET - 1)];
    int p0 = atomicAdd(&cur[d4.x], 1);
    int p1 = atomicAdd(&cur[d4.y], 1);
    int p2 = atomicAdd(&cur[d4.z], 1);
    int p3 = atomicAdd(&cur[d4.w], 1);
    g_csr_src[p0] = s4.x;
    g_csr_src[p1] = s4.y;
    g_csr_src[p2] = s4.z;
    g_csr_src[p3] = s4.w;
}

// ---------------- GEMM1: h1 = x @ W1, s1/d1 attention projections ----------------
__global__ __launch_bounds__(256) void k_gemm1(const float* __restrict__ x,
                                               const float* __restrict__ W1,
                                               const float* __restrict__ a_src,
                                               const float* __restrict__ a_dst) {
    __shared__ float Ws[F_IN * HID];
    __shared__ float asv[HID], adv[HID];
    for (int i = threadIdx.x; i < F_IN * HID; i += blockDim.x) Ws[i] = W1[i];
    if (threadIdx.x < HID) { asv[threadIdx.x] = a_src[threadIdx.x]; adv[threadIdx.x] = a_dst[threadIdx.x]; }
    __syncthreads();

    int n = blockIdx.x * blockDim.x + threadIdx.x;
    if (n >= N_NODES) return;

    float acc[HID];
#pragma unroll
    for (int c = 0; c < HID; c++) acc[c] = 0.f;

    const float4* xr = reinterpret_cast<const float4*>(x + (size_t)n * F_IN);
    const float4* Ws4 = reinterpret_cast<const float4*>(Ws);
#pragma unroll 4
    for (int k4 = 0; k4 < F_IN / 4; k4++) {
        float4 xv = xr[k4];
        int r = (k4 * 4) * (HID / 4);
#pragma unroll
        for (int c4 = 0; c4 < HID / 4; c4++) {
            float4 w0 = Ws4[r + c4];
            float4 w1 = Ws4[r + (HID / 4) + c4];
            float4 w2 = Ws4[r + 2 * (HID / 4) + c4];
            float4 w3 = Ws4[r + 3 * (HID / 4) + c4];
            int c = c4 * 4;
            acc[c+0] = fmaf(xv.x, w0.x, fmaf(xv.y, w1.x, fmaf(xv.z, w2.x, fmaf(xv.w, w3.x, acc[c+0]))));
            acc[c+1] = fmaf(xv.x, w0.y, fmaf(xv.y, w1.y, fmaf(xv.z, w2.y, fmaf(xv.w, w3.y, acc[c+1]))));
            acc[c+2] = fmaf(xv.x, w0.z, fmaf(xv.y, w1.z, fmaf(xv.z, w2.z, fmaf(xv.w, w3.z, acc[c+2]))));
            acc[c+3] = fmaf(xv.x, w0.w, fmaf(xv.y, w1.w, fmaf(xv.z, w2.w, fmaf(xv.w, w3.w, acc[c+3]))));
        }
    }
    float sv = 0.f, dv = 0.f;
#pragma unroll
    for (int c = 0; c < HID; c++) {
        g_h1[(size_t)n * HID + c] = acc[c];
        sv = fmaf(acc[c], asv[c], sv);
        dv = fmaf(acc[c], adv[c], dv);
    }
    g_s1[n] = sv;
    g_d1[n] = dv;
}

// ---- layer-1 aggregate: warp/dst, no-max softmax (logits bounded), smem broadcast ----
__global__ __launch_bounds__(256) void k_agg1(const float* __restrict__ b1) {
    __shared__ float2 shp[8][2][32];
    int tid = threadIdx.x;
    int wib = tid >> 5;
    int lane = tid & 31;
    int n = (blockIdx.x * blockDim.x + tid) >> 5;
    if (n >= N_NODES) return;
    int beg = g_rowptr[n], end = g_rowptr[n + 1];
    float dn = g_d1[n];

    float denl = 0.f, acc0 = 0.f, acc1 = 0.f;
    int buf = 0;

    for (int base = beg; base < end; base += 32, buf ^= 1) {
        int c = min(32, end - base);
        bool valid = lane < c;
        int idx = g_csr_src[base + (valid ? lane : 0)];  // coalesced
        float ev = g_s1[idx] + dn;
        ev = ev > 0.f ? ev : NEG_SLOPE * ev;
        float p = valid ? __expf(ev) : 0.f;
        denl += p;

        shp[wib][buf][lane] = make_float2(p, __int_as_float(idx * HID));
        __syncwarp();
        const float2* pr = shp[wib][buf];
        int j = 0;
        for (; j + 4 <= c; j += 4) {
            float2 q0 = pr[j], q1 = pr[j+1], q2 = pr[j+2], q3 = pr[j+3];
            acc0 = fmaf(q0.x, g_h1[__float_as_int(q0.y) + lane], acc0);
            acc1 = fmaf(q1.x, g_h1[__float_as_int(q1.y) + lane], acc1);
            acc0 = fmaf(q2.x, g_h1[__float_as_int(q2.y) + lane], acc0);
            acc1 = fmaf(q3.x, g_h1[__float_as_int(q3.y) + lane], acc1);
        }
        for (; j < c; j++) {
            float2 q = pr[j];
            acc0 = fmaf(q.x, g_h1[__float_as_int(q.y) + lane], acc0);
        }
    }

    float den = denl;
#pragma unroll
    for (int o = 16; o > 0; o >>= 1) den += __shfl_xor_sync(0xffffffffu, den, o);

    float v = fmaxf((acc0 + acc1) / den + b1[lane], 0.f);
    g_x2[(size_t)n * HID + lane] = v;

    // epilogue: s2/d2 projections for layer 2 (gemm2 fused away)
    float sp = v * g_w2s[lane];
    float dp = v * g_w2d[lane];
#pragma unroll
    for (int o = 16; o > 0; o >>= 1) {
        sp += __shfl_xor_sync(0xffffffffu, sp, o);
        dp += __shfl_xor_sync(0xffffffffu, dp, o);
    }
    if (lane == 0) { g_s2[n] = sp; g_d2[n] = dp; }
}

// ---- layer-2: aggregate x2, epilogue W2 GEMM + bias + relu + log_softmax ----
__global__ __launch_bounds__(256) void k_agg2(const float* __restrict__ W2,
                                              const float* __restrict__ b2,
                                              float* __restrict__ out) {
    __shared__ float W2s[HID * NCLS];
    __shared__ float2 shp[8][2][32];
    for (int i = threadIdx.x; i < HID * NCLS; i += blockDim.x) W2s[i] = W2[i];
    __syncthreads();

    int tid = threadIdx.x;
    int wib = tid >> 5;
    int lane = tid & 31;
    int n = (blockIdx.x * blockDim.x + tid) >> 5;
    if (n >= N_NODES) return;
    bool has2 = lane < (NCLS - 32);
    int beg = g_rowptr[n], end = g_rowptr[n + 1];
    float dn = g_d2[n];

    float denl = 0.f, acc0 = 0.f, acc1 = 0.f;
    int buf = 0;

    for (int base = beg; base < end; base += 32, buf ^= 1) {
        int c = min(32, end - base);
        bool valid = lane < c;
        int idx = g_csr_src[base + (valid ? lane : 0)];
        float ev = g_s2[idx] + dn;
        ev = ev > 0.f ? ev : NEG_SLOPE * ev;
        float p = valid ? __expf(ev) : 0.f;
        denl += p;

        shp[wib][buf][lane] = make_float2(p, __int_as_float(idx * HID));
        __syncwarp();
        const float2* pr = shp[wib][buf];
        int j = 0;
        for (; j + 4 <= c; j += 4) {
            float2 q0 = pr[j], q1 = pr[j+1], q2 = pr[j+2], q3 = pr[j+3];
            acc0 = fmaf(q0.x, g_x2[__float_as_int(q0.y) + lane], acc0);
            acc1 = fmaf(q1.x, g_x2[__float_as_int(q1.y) + lane], acc1);
            acc0 = fmaf(q2.x, g_x2[__float_as_int(q2.y) + lane], acc0);
            acc1 = fmaf(q3.x, g_x2[__float_as_int(q3.y) + lane], acc1);
        }
        for (; j < c; j++) {
            float2 q = pr[j];
            acc0 = fmaf(q.x, g_x2[__float_as_int(q.y) + lane], acc0);
        }
    }

    float den = denl;
#pragma unroll
    for (int o = 16; o > 0; o >>= 1) den += __shfl_xor_sync(0xffffffffu, den, o);

    float aggx = (acc0 + acc1) / den;   // aggregated x2, lane = channel

    // epilogue GEMM: h_out[c] = sum_k aggx_k * W2[k][c] + b2[c]
    float o0 = b2[lane];
    float o1 = has2 ? b2[lane + 32] : 0.f;
#pragma unroll
    for (int k = 0; k < HID; k++) {
        float xk = __shfl_sync(0xffffffffu, aggx, k);
        o0 = fmaf(xk, W2s[k * NCLS + lane], o0);
        if (has2) o1 = fmaf(xk, W2s[k * NCLS + lane + 32], o1);
    }
    float v0 = fmaxf(o0, 0.f);
    float v1 = has2 ? fmaxf(o1, 0.f) : -CUDART_INF_F;

    float m = fmaxf(v0, v1);
#pragma unroll
    for (int o = 16; o > 0; o >>= 1) m = fmaxf(m, __shfl_xor_sync(0xffffffffu, m, o));
    float se = __expf(v0 - m) + (has2 ? __expf(v1 - m) : 0.f);
#pragma unroll
    for (int o = 16; o > 0; o >>= 1) se += __shfl_xor_sync(0xffffffffu, se, o);
    float lse = m + logf(se);

    out[(size_t)n * NCLS + lane] = v0 - lse;
    if (has2) out[(size_t)n * NCLS + lane + 32] = v1 - lse;
}

// ---------------- launch ----------------
extern "C" void kernel_launch(void* const* d_in, const int* in_sizes, int n_in,
                              void* d_out, int out_size) {
    const float* x        = (const float*)d_in[0];
    const int*   edge     = (const int*)  d_in[1];
    const float* W1       = (const float*)d_in[2];
    const float* att_src1 = (const float*)d_in[3];
    const float* att_dst1 = (const float*)d_in[4];
    const float* b1       = (const float*)d_in[5];
    const float* W2       = (const float*)d_in[6];
    const float* att_src2 = (const float*)d_in[7];
    const float* att_dst2 = (const float*)d_in[8];
    const float* b2       = (const float*)d_in[9];
    float* out = (float*)d_out;

    const int* src = edge;
    const int* dst = edge + N_EDGES;

    // cache device addresses + side stream on first (non-captured) call
    static cudaStream_t s2 = nullptr;
    static cudaEvent_t evFork = nullptr, evJoin = nullptr;
    static void* degAddr = nullptr;
    static void* readyAddr = nullptr;
    if (!s2) {
        cudaStreamCreateWithFlags(&s2, cudaStreamNonBlocking);
        cudaEventCreateWithFlags(&evFork, cudaEventDisableTiming);
        cudaEventCreateWithFlags(&evJoin, cudaEventDisableTiming);
        cudaGetSymbolAddress(&degAddr, g_deg);
        cudaGetSymbolAddress(&readyAddr, g_ready);
    }

    // fork: gemm1 + prep are independent of the CSR build
    cudaEventRecord(evFork, 0);
    cudaStreamWaitEvent(s2, evFork, 0);
    k_prep<<<1, 32, 0, s2>>>(W2, att_src2, att_dst2);
    k_gemm1<<<(N_NODES + 255) / 256, 256, 0, s2>>>(x, W1, att_src1, att_dst1);
    cudaEventRecord(evJoin, s2);

    // main stream: CSR build
    cudaMemsetAsync(degAddr, 0, sizeof(int) * NBUCKET * N_NODES, 0);
    cudaMemsetAsync(readyAddr, 0, sizeof(int), 0);
    k_hist<<<(NQUAD + 255) / 256, 256>>>(dst);
    k_scan<<<NBLK_SCAN, 256>>>();
    k_scatter<<<(NQUAD + 255) / 256, 256>>>(src, dst);

    // join, then aggregates
    cudaStreamWaitEvent(0, evJoin, 0);
    k_agg1<<<(N_NODES * 32 + 255) / 256, 256>>>(b1);
    k_agg2<<<(N_NODES * 32 + 255) / 256, 256>>>(W2, b2, out);
}